// round 2
// baseline (speedup 1.0000x reference)
#include <cuda_runtime.h>
#include <cuda_bf16.h>

// ---------------------------------------------------------------------------
// gMamba: conv/BN front-end -> (Mamba selective scan final state) + (biGRU)
// Only output[:, -1, :] feeds pred, so the selective scan is reduced to its
// final state (chunk-parallel linear recurrence). The GRU is the serial wall:
// one warp per direction, input projections precomputed in parallel.
// ---------------------------------------------------------------------------

#define LSEQ   65536
#define DM     12
#define DI     24
#define DS     16
#define CINCH  64
#define CMID   32
#define HG     6
#define G3     (3*HG)          // 18
#define T_CHUNK 128
#define NCHUNK (LSEQ / T_CHUNK)   // 512
#define NPAIR  (DI * DS)          // 384

// ------------------------- scratch (static device globals) -----------------
__device__ float g_seq[LSEQ * DM];            // 3.1 MB
__device__ float g_gi[2 * LSEQ * G3];         // 9.4 MB
__device__ float g_cA[NCHUNK * NPAIR];
__device__ float g_cB[NCHUNK * NPAIR];
__device__ float g_hf[HG];
__device__ float g_hb[HG];
__device__ float g_hb1[HG];

// ------------------------- helpers -----------------------------------------
__device__ __forceinline__ float frcp(float x) {
    float y; asm("rcp.approx.f32 %0, %1;" : "=f"(y) : "f"(x)); return y;
}
__device__ __forceinline__ float sigm(float x) {   // accurate: ex2 + rcp
    return frcp(1.0f + __expf(-x));
}
__device__ __forceinline__ float softplusf(float x) {
    return (x > 15.0f) ? x : __logf(1.0f + __expf(x));
}

// ------------------------- K1: conv1->bn1->relu->conv2->bn2->relu -----------
__global__ void k_seq(const float* __restrict__ x,
                      const float* __restrict__ w1, const float* __restrict__ cb1,
                      const float* __restrict__ bg1, const float* __restrict__ bb1,
                      const float* __restrict__ bm1, const float* __restrict__ bv1,
                      const float* __restrict__ w2, const float* __restrict__ cb2,
                      const float* __restrict__ bg2, const float* __restrict__ bb2,
                      const float* __restrict__ bm2, const float* __restrict__ bv2)
{
    __shared__ float sw[CMID * CINCH];
    __shared__ float ss1[CMID], st1[CMID], sw2[CMID];
    int tid = threadIdx.x;
    for (int i = tid; i < CMID * CINCH; i += blockDim.x) sw[i] = w1[i];
    if (tid < CMID) {
        float s = bg1[tid] * rsqrtf(bv1[tid] + 1e-5f);
        ss1[tid] = s;
        st1[tid] = fmaf(cb1[tid], s, bb1[tid] - bm1[tid] * s);
        sw2[tid] = w2[tid];
    }
    __syncthreads();

    int pos = blockIdx.x * blockDim.x + tid;
    if (pos >= LSEQ * DM) return;

    float acc[CMID];
#pragma unroll
    for (int m = 0; m < CMID; m++) acc[m] = 0.0f;

    const float* xp = x + pos;
#pragma unroll 4
    for (int c = 0; c < CINCH; c++) {
        float xv = xp[(size_t)c * (LSEQ * DM)];
#pragma unroll
        for (int m = 0; m < CMID; m++)
            acc[m] = fmaf(xv, sw[m * CINCH + c], acc[m]);
    }
    float a2 = 0.0f;
#pragma unroll
    for (int m = 0; m < CMID; m++) {
        float v = fmaf(acc[m], ss1[m], st1[m]);
        v = fmaxf(v, 0.0f);
        a2 = fmaf(v, sw2[m], a2);
    }
    float s2 = bg2[0] * rsqrtf(bv2[0] + 1e-5f);
    float o  = fmaf(a2 + cb2[0], s2, bb2[0] - bm2[0] * s2);
    g_seq[pos] = fmaxf(o, 0.0f);
}

// ------------------------- K2: GRU input projections (both directions) ------
__global__ void k_gi(const float* __restrict__ Wih, const float* __restrict__ bih)
{
    int idx = blockIdx.x * blockDim.x + threadIdx.x;   // [0, 2L)
    if (idx >= 2 * LSEQ) return;
    int dir = idx >> 16;                 // LSEQ == 65536
    int t   = idx & (LSEQ - 1);
    int ts  = dir ? (LSEQ - 1 - t) : t;

    float sv[DM];
#pragma unroll
    for (int w = 0; w < DM; w++) sv[w] = g_seq[ts * DM + w];

    const float* Wd = Wih + dir * G3 * DM;
    const float* bd = bih + dir * G3;
    float* out = g_gi + ((size_t)(dir * LSEQ + t)) * G3;
#pragma unroll
    for (int j = 0; j < G3; j++) {
        float a = bd[j];
#pragma unroll
        for (int w = 0; w < DM; w++)
            a = fmaf(sv[w], __ldg(Wd + j * DM + w), a);
        out[j] = a;
    }
}

// ------------------------- K3: Mamba per-chunk linear-recurrence factors ----
__global__ void k_chunk(const float* __restrict__ ipw, const float* __restrict__ c1w,
                        const float* __restrict__ c1b, const float* __restrict__ xpw,
                        const float* __restrict__ dtw, const float* __restrict__ dtb,
                        const float* __restrict__ A_log)
{
    __shared__ float seqs[(T_CHUNK + 3) * DM];   // halo of 3 rows for causal conv
    __shared__ float u_s[T_CHUNK * DI];
    __shared__ float dl_s[T_CHUNK * DI];
    __shared__ float B_s[T_CHUNK * DS];
    __shared__ float dt_s[T_CHUNK];

    int tid = threadIdx.x;
    int t0  = blockIdx.x * T_CHUNK;

    for (int i = tid; i < (T_CHUNK + 3) * DM; i += blockDim.x) {
        int r = i / DM, w = i % DM;
        int tt = t0 - 3 + r;
        seqs[i] = (tt < 0) ? 0.0f : g_seq[tt * DM + w];
    }
    __syncthreads();

    // u = silu(depthwise_causal_conv(seq @ in_proj[0:24]) + b)
    for (int it = tid; it < T_CHUNK * DI; it += blockDim.x) {
        int tl = it / DI, d = it % DI;
        float wr[DM];
#pragma unroll
        for (int w = 0; w < DM; w++) wr[w] = __ldg(ipw + d * DM + w);
        float conv = 0.0f;
#pragma unroll
        for (int k = 0; k < 4; k++) {
            const float* srow = seqs + (tl + k) * DM;  // local row tl+k == global t0+tl-3+k
            float xm = 0.0f;
#pragma unroll
            for (int w = 0; w < DM; w++) xm = fmaf(srow[w], wr[w], xm);
            conv = fmaf(xm, __ldg(c1w + d * 4 + k), conv);
        }
        float xc = conv + __ldg(c1b + d);
        u_s[it] = xc * sigm(xc);
    }
    __syncthreads();

    // x_dbl: dt (j==0) and B (j in 1..16); C is only needed at t=L-1 (finalize)
    for (int it = tid; it < T_CHUNK * 17; it += blockDim.x) {
        int tl = it / 17, j = it % 17;
        float a = 0.0f;
        const float* up = u_s + tl * DI;
#pragma unroll
        for (int d = 0; d < DI; d++) a = fmaf(up[d], __ldg(xpw + j * DI + d), a);
        if (j == 0) dt_s[tl] = a; else B_s[tl * DS + (j - 1)] = a;
    }
    __syncthreads();

    // delta = softplus(dt * dt_proj_w + dt_proj_b)
    for (int it = tid; it < T_CHUNK * DI; it += blockDim.x) {
        int tl = it / DI, d = it % DI;
        dl_s[it] = softplusf(fmaf(dt_s[tl], __ldg(dtw + d), __ldg(dtb + d)));
    }
    __syncthreads();

    // per-(d,n) chunk factors: h_out = Ap*h_in + Bc
    if (tid < NPAIR) {
        int d = tid >> 4, n = tid & 15;
        float Adn = -__expf(__ldg(A_log + tid));   // A_log row-major (24,16)
        float Ap = 1.0f, Bc = 0.0f;
#pragma unroll 4
        for (int t = 0; t < T_CHUNK; t++) {
            float dl = dl_s[t * DI + d];
            float a  = __expf(dl * Adn);
            float bv = dl * B_s[t * DS + n] * u_s[t * DI + d];
            Bc = fmaf(a, Bc, bv);
            Ap *= a;
        }
        g_cA[blockIdx.x * NPAIR + tid] = Ap;
        g_cB[blockIdx.x * NPAIR + tid] = Bc;
    }
}

// ------------------------- K4: serial GRU (the latency wall) ----------------
// One block (one warp) per direction. Lane j<18 owns gate j; lanes hold
// h_{lane%6}; h is rebroadcast each step via 6 shuffles. gi is prefetched
// 8 steps ahead to hide L2/DRAM latency.
__global__ void k_gru(const float* __restrict__ Whh, const float* __restrict__ bhh,
                      const float* __restrict__ hidden)
{
    const unsigned FULL = 0xFFFFFFFFu;
    int dir  = blockIdx.x;
    int lane = threadIdx.x;
    int jj   = lane % G3;
    int l6   = lane % 6;

    float w0 = Whh[(dir * G3 + jj) * HG + 0];
    float w1 = Whh[(dir * G3 + jj) * HG + 1];
    float w2 = Whh[(dir * G3 + jj) * HG + 2];
    float w3 = Whh[(dir * G3 + jj) * HG + 3];
    float w4 = Whh[(dir * G3 + jj) * HG + 4];
    float w5 = Whh[(dir * G3 + jj) * HG + 5];
    float bh = bhh[dir * G3 + jj];
    float hcur = hidden[dir * HG + l6];

    const float* gip = g_gi + (size_t)dir * LSEQ * G3 + jj;

    float buf[8];
#pragma unroll
    for (int k = 0; k < 8; k++) buf[k] = __ldg(gip + k * G3);

    for (int t = 0; t < LSEQ; t += 8) {
#pragma unroll
        for (int k = 0; k < 8; k++) {
            float giv = buf[k];
            int tn = t + 8 + k;
            if (tn < LSEQ) buf[k] = __ldg(gip + (size_t)tn * G3);

            float h0 = __shfl_sync(FULL, hcur, 0);
            float h1 = __shfl_sync(FULL, hcur, 1);
            float h2 = __shfl_sync(FULL, hcur, 2);
            float h3 = __shfl_sync(FULL, hcur, 3);
            float h4 = __shfl_sync(FULL, hcur, 4);
            float h5 = __shfl_sync(FULL, hcur, 5);

            float p = fmaf(w0, h0, bh); p = fmaf(w1, h1, p); p = fmaf(w2, h2, p);
            float q = w3 * h3;          q = fmaf(w4, h4, q); q = fmaf(w5, h5, q);
            float g = p + q;                       // gh_jj (incl. bhh)
            float xs = giv + g;
            float s  = sigm(xs);                   // valid for r/z lanes

            float zz  = __shfl_sync(FULL, s,   l6 + 6);
            float gn  = __shfl_sync(FULL, g,   l6 + 12);
            float gin = __shfl_sync(FULL, giv, l6 + 12);
            float r   = __shfl_sync(FULL, s,   l6);

            float narg = fmaf(r, gn, gin);
            float nt = fmaf(2.0f, frcp(1.0f + __expf(-2.0f * narg)), -1.0f);  // tanh
            hcur = fmaf(zz, hcur - nt, nt);        // (1-z)*n + z*h

            if (dir == 1 && (t + k) == 0 && lane < 6) g_hb1[lane] = hcur;
        }
    }
    if (lane < 6) {
        if (dir == 0) g_hf[lane] = hcur;
        else          g_hb[lane] = hcur;
    }
}

// ------------------------- K5: combine chunks + epilogue --------------------
__global__ void k_final(const float* __restrict__ ipw, const float* __restrict__ c1w,
                        const float* __restrict__ c1b, const float* __restrict__ xpw,
                        const float* __restrict__ opw, const float* __restrict__ Dp,
                        const float* __restrict__ lw,  const float* __restrict__ lb,
                        float* __restrict__ out, int out_size)
{
    __shared__ float hs[NPAIR];
    __shared__ float us[DI], sres[DI], cs[DS], gs[DI], os[DM];
    int tid = threadIdx.x;

    if (tid < NPAIR) {
        float h = 0.0f;
#pragma unroll 4
        for (int ch = 0; ch < NCHUNK; ch++)
            h = fmaf(g_cA[ch * NPAIR + tid], h, g_cB[ch * NPAIR + tid]);
        hs[tid] = h;
    }
    __syncthreads();

    if (tid < DI) {
        int d = tid;
        float wr[DM];
#pragma unroll
        for (int w = 0; w < DM; w++) wr[w] = ipw[d * DM + w];
        float conv = 0.0f;
#pragma unroll
        for (int k = 0; k < 4; k++) {
            const float* srow = g_seq + (LSEQ - 4 + k) * DM;   // t = L-4+k
            float xm = 0.0f;
#pragma unroll
            for (int w = 0; w < DM; w++) xm = fmaf(srow[w], wr[w], xm);
            conv = fmaf(xm, c1w[d * 4 + k], conv);
        }
        float xc = conv + c1b[d];
        us[d] = xc * sigm(xc);

        float rr = 0.0f;
        const float* sl = g_seq + (LSEQ - 1) * DM;
#pragma unroll
        for (int w = 0; w < DM; w++) rr = fmaf(sl[w], ipw[(DI + d) * DM + w], rr);
        sres[d] = rr * sigm(rr);
    }
    __syncthreads();

    if (tid < DS) {                           // C at t=L-1
        float a = 0.0f;
#pragma unroll
        for (int d = 0; d < DI; d++) a = fmaf(us[d], xpw[(17 + tid) * DI + d], a);
        cs[tid] = a;
    }
    __syncthreads();

    if (tid < DI) {                           // y[L-1] and gate
        float y = 0.0f;
#pragma unroll
        for (int n = 0; n < DS; n++) y = fmaf(hs[tid * DS + n], cs[n], y);
        y = fmaf(us[tid], Dp[tid], y);
        gs[tid] = y * sres[tid];
    }
    __syncthreads();

    if (tid < DM) {                           // out1[L-1] + out2[L-1]
        float o = 0.0f;
#pragma unroll
        for (int d = 0; d < DI; d++) o = fmaf(gs[d], opw[tid * DI + d], o);
        o += (tid < 6) ? g_hf[tid] : g_hb1[tid - 6];
        os[tid] = o;
    }
    __syncthreads();

    if (tid == 0) {
        float p = lb[0];
#pragma unroll
        for (int w = 0; w < DM; w++) p = fmaf(os[w], lw[w], p);
        if (out_size > 0) out[0] = p;
    }
    if (tid < 6) {
        if (1 + tid < out_size) out[1 + tid] = g_hf[tid];
        if (7 + tid < out_size) out[7 + tid] = g_hb[tid];
    }
}

// ------------------------- launch -------------------------------------------
extern "C" void kernel_launch(void* const* d_in, const int* in_sizes, int n_in,
                              void* d_out, int out_size)
{
    const float* x    = (const float*)d_in[0];
    const float* hid  = (const float*)d_in[1];
    const float* c1w_ = (const float*)d_in[2];
    const float* c1b_ = (const float*)d_in[3];
    const float* bg1  = (const float*)d_in[4];
    const float* bb1  = (const float*)d_in[5];
    const float* bm1  = (const float*)d_in[6];
    const float* bv1  = (const float*)d_in[7];
    const float* c2w  = (const float*)d_in[8];
    const float* c2b  = (const float*)d_in[9];
    const float* bg2  = (const float*)d_in[10];
    const float* bb2  = (const float*)d_in[11];
    const float* bm2  = (const float*)d_in[12];
    const float* bv2  = (const float*)d_in[13];
    const float* ipw  = (const float*)d_in[14];
    const float* cd1w = (const float*)d_in[15];
    const float* cd1b = (const float*)d_in[16];
    const float* xpw  = (const float*)d_in[17];
    const float* dtw  = (const float*)d_in[18];
    const float* dtb  = (const float*)d_in[19];
    const float* Alog = (const float*)d_in[20];
    const float* Dp   = (const float*)d_in[21];
    const float* opw  = (const float*)d_in[22];
    const float* Wih  = (const float*)d_in[23];
    const float* Whh  = (const float*)d_in[24];
    const float* bih  = (const float*)d_in[25];
    const float* bhh  = (const float*)d_in[26];
    const float* lw   = (const float*)d_in[27];
    const float* lb   = (const float*)d_in[28];
    float* out = (float*)d_out;

    k_seq<<<(LSEQ * DM) / 256, 256>>>(x, c1w_, c1b_, bg1, bb1, bm1, bv1,
                                      c2w, c2b, bg2, bb2, bm2, bv2);
    k_gi<<<(2 * LSEQ) / 256, 256>>>(Wih, bih);
    k_chunk<<<NCHUNK, 384>>>(ipw, cd1w, cd1b, xpw, dtw, dtb, Alog);
    k_gru<<<2, 32>>>(Whh, bhh, hid);
    k_final<<<1, 384>>>(ipw, cd1w, cd1b, xpw, opw, Dp, lw, lb, out, out_size);
}

// round 3
// speedup vs baseline: 1.7181x; 1.7181x over previous
#include <cuda_runtime.h>
#include <cuda_bf16.h>

// ---------------------------------------------------------------------------
// gMamba: conv/BN front-end -> (Mamba selective scan final state) + (biGRU)
// R2: GRU restructured to ONE shuffle round per step (each lane computes all
// three of its gates) + MUFU tanh.approx activations + float4 gi loads.
// ---------------------------------------------------------------------------

#define LSEQ   65536
#define DM     12
#define DI     24
#define DS     16
#define CINCH  64
#define CMID   32
#define HG     6
#define G3     (3*HG)          // 18
#define T_CHUNK 128
#define NCHUNK (LSEQ / T_CHUNK)   // 512
#define NPAIR  (DI * DS)          // 384

// ------------------------- scratch (static device globals) -----------------
__device__ float  g_seq[LSEQ * DM];              // 3.1 MB
__device__ float4 g_gi4[2 * LSEQ * HG];          // 12.6 MB: {gi_r, gi_z, gi_n, 0}
__device__ float  g_cA[NCHUNK * NPAIR];
__device__ float  g_cB[NCHUNK * NPAIR];
__device__ float  g_hf[HG];
__device__ float  g_hb[HG];
__device__ float  g_hb1[HG];

// ------------------------- helpers -----------------------------------------
__device__ __forceinline__ float frcp(float x) {
    float y; asm("rcp.approx.f32 %0, %1;" : "=f"(y) : "f"(x)); return y;
}
__device__ __forceinline__ float tanh_mufu(float x) {
    float y; asm("tanh.approx.f32 %0, %1;" : "=f"(y) : "f"(x)); return y;
}
__device__ __forceinline__ float sigm(float x) {   // accurate: ex2 + rcp
    return frcp(1.0f + __expf(-x));
}
__device__ __forceinline__ float softplusf(float x) {
    return (x > 15.0f) ? x : __logf(1.0f + __expf(x));
}

// ------------------------- K1: conv1->bn1->relu->conv2->bn2->relu -----------
__global__ void k_seq(const float* __restrict__ x,
                      const float* __restrict__ w1, const float* __restrict__ cb1,
                      const float* __restrict__ bg1, const float* __restrict__ bb1,
                      const float* __restrict__ bm1, const float* __restrict__ bv1,
                      const float* __restrict__ w2, const float* __restrict__ cb2,
                      const float* __restrict__ bg2, const float* __restrict__ bb2,
                      const float* __restrict__ bm2, const float* __restrict__ bv2)
{
    __shared__ float sw[CMID * CINCH];
    __shared__ float ss1[CMID], st1[CMID], sw2[CMID];
    int tid = threadIdx.x;
    for (int i = tid; i < CMID * CINCH; i += blockDim.x) sw[i] = w1[i];
    if (tid < CMID) {
        float s = bg1[tid] * rsqrtf(bv1[tid] + 1e-5f);
        ss1[tid] = s;
        st1[tid] = fmaf(cb1[tid], s, bb1[tid] - bm1[tid] * s);
        sw2[tid] = w2[tid];
    }
    __syncthreads();

    int pos = blockIdx.x * blockDim.x + tid;
    if (pos >= LSEQ * DM) return;

    float acc[CMID];
#pragma unroll
    for (int m = 0; m < CMID; m++) acc[m] = 0.0f;

    const float* xp = x + pos;
#pragma unroll 4
    for (int c = 0; c < CINCH; c++) {
        float xv = xp[(size_t)c * (LSEQ * DM)];
#pragma unroll
        for (int m = 0; m < CMID; m++)
            acc[m] = fmaf(xv, sw[m * CINCH + c], acc[m]);
    }
    float a2 = 0.0f;
#pragma unroll
    for (int m = 0; m < CMID; m++) {
        float v = fmaf(acc[m], ss1[m], st1[m]);
        v = fmaxf(v, 0.0f);
        a2 = fmaf(v, sw2[m], a2);
    }
    float s2 = bg2[0] * rsqrtf(bv2[0] + 1e-5f);
    float o  = fmaf(a2 + cb2[0], s2, bb2[0] - bm2[0] * s2);
    g_seq[pos] = fmaxf(o, 0.0f);
}

// ------------------------- K2: GRU input projections (both directions) ------
// Output layout: g_gi4[(dir*L + t)*6 + i] = {gi_r[i], gi_z[i], gi_n[i], 0}
__global__ void k_gi(const float* __restrict__ Wih, const float* __restrict__ bih)
{
    int idx = blockIdx.x * blockDim.x + threadIdx.x;   // [0, 2L)
    if (idx >= 2 * LSEQ) return;
    int dir = idx >> 16;                 // LSEQ == 65536
    int t   = idx & (LSEQ - 1);
    int ts  = dir ? (LSEQ - 1 - t) : t;

    float sv[DM];
#pragma unroll
    for (int w = 0; w < DM; w++) sv[w] = g_seq[ts * DM + w];

    const float* Wd = Wih + dir * G3 * DM;
    const float* bd = bih + dir * G3;
    float4* out = g_gi4 + ((size_t)(dir * LSEQ + t)) * HG;
#pragma unroll
    for (int i = 0; i < HG; i++) {
        float4 v;
        float ar = bd[i], az = bd[HG + i], an = bd[2 * HG + i];
#pragma unroll
        for (int w = 0; w < DM; w++) {
            ar = fmaf(sv[w], __ldg(Wd + i * DM + w), ar);
            az = fmaf(sv[w], __ldg(Wd + (HG + i) * DM + w), az);
            an = fmaf(sv[w], __ldg(Wd + (2 * HG + i) * DM + w), an);
        }
        v.x = ar; v.y = az; v.z = an; v.w = 0.0f;
        out[i] = v;
    }
}

// ------------------------- K3: Mamba per-chunk linear-recurrence factors ----
__global__ void k_chunk(const float* __restrict__ ipw, const float* __restrict__ c1w,
                        const float* __restrict__ c1b, const float* __restrict__ xpw,
                        const float* __restrict__ dtw, const float* __restrict__ dtb,
                        const float* __restrict__ A_log)
{
    __shared__ float seqs[(T_CHUNK + 3) * DM];   // halo of 3 rows for causal conv
    __shared__ float u_s[T_CHUNK * DI];
    __shared__ float dl_s[T_CHUNK * DI];
    __shared__ float B_s[T_CHUNK * DS];
    __shared__ float dt_s[T_CHUNK];

    int tid = threadIdx.x;
    int t0  = blockIdx.x * T_CHUNK;

    for (int i = tid; i < (T_CHUNK + 3) * DM; i += blockDim.x) {
        int r = i / DM, w = i % DM;
        int tt = t0 - 3 + r;
        seqs[i] = (tt < 0) ? 0.0f : g_seq[tt * DM + w];
    }
    __syncthreads();

    // u = silu(depthwise_causal_conv(seq @ in_proj[0:24]) + b)
    for (int it = tid; it < T_CHUNK * DI; it += blockDim.x) {
        int tl = it / DI, d = it % DI;
        float wr[DM];
#pragma unroll
        for (int w = 0; w < DM; w++) wr[w] = __ldg(ipw + d * DM + w);
        float conv = 0.0f;
#pragma unroll
        for (int k = 0; k < 4; k++) {
            const float* srow = seqs + (tl + k) * DM;
            float xm = 0.0f;
#pragma unroll
            for (int w = 0; w < DM; w++) xm = fmaf(srow[w], wr[w], xm);
            conv = fmaf(xm, __ldg(c1w + d * 4 + k), conv);
        }
        float xc = conv + __ldg(c1b + d);
        u_s[it] = xc * sigm(xc);
    }
    __syncthreads();

    // x_dbl: dt (j==0) and B (j in 1..16)
    for (int it = tid; it < T_CHUNK * 17; it += blockDim.x) {
        int tl = it / 17, j = it % 17;
        float a = 0.0f;
        const float* up = u_s + tl * DI;
#pragma unroll
        for (int d = 0; d < DI; d++) a = fmaf(up[d], __ldg(xpw + j * DI + d), a);
        if (j == 0) dt_s[tl] = a; else B_s[tl * DS + (j - 1)] = a;
    }
    __syncthreads();

    // delta = softplus(dt * dt_proj_w + dt_proj_b)
    for (int it = tid; it < T_CHUNK * DI; it += blockDim.x) {
        int tl = it / DI, d = it % DI;
        dl_s[it] = softplusf(fmaf(dt_s[tl], __ldg(dtw + d), __ldg(dtb + d)));
    }
    __syncthreads();

    // per-(d,n) chunk factors: h_out = Ap*h_in + Bc
    if (tid < NPAIR) {
        int d = tid >> 4, n = tid & 15;
        float Adn = -__expf(__ldg(A_log + tid));
        float Ap = 1.0f, Bc = 0.0f;
#pragma unroll 4
        for (int t = 0; t < T_CHUNK; t++) {
            float dl = dl_s[t * DI + d];
            float a  = __expf(dl * Adn);
            float bv = dl * B_s[t * DS + n] * u_s[t * DI + d];
            Bc = fmaf(a, Bc, bv);
            Ap *= a;
        }
        g_cA[blockIdx.x * NPAIR + tid] = Ap;
        g_cB[blockIdx.x * NPAIR + tid] = Bc;
    }
}

// ------------------------- K4: serial GRU (the latency wall) ----------------
// One warp per direction. Lane i (=lane%6) owns h_i and computes ALL THREE of
// its gates (r_i, z_i, n_i) from the broadcast h — exactly one shuffle round
// per step. Activations via MUFU tanh.approx. gi prefetched 8 steps ahead as
// one float4 per step.
__global__ void k_gru(const float* __restrict__ Whh, const float* __restrict__ bhh,
                      const float* __restrict__ hidden)
{
    const unsigned FULL = 0xFFFFFFFFu;
    int dir  = blockIdx.x;
    int lane = threadIdx.x;
    int l6   = lane % HG;

    const float* Wd = Whh + dir * G3 * HG;
    float wr[HG], wz[HG], wn[HG];
#pragma unroll
    for (int j = 0; j < HG; j++) {
        wr[j] = Wd[l6 * HG + j];
        wz[j] = Wd[(HG + l6) * HG + j];
        wn[j] = Wd[(2 * HG + l6) * HG + j];
    }
    float br = bhh[dir * G3 + l6];
    float bz = bhh[dir * G3 + HG + l6];
    float bn = bhh[dir * G3 + 2 * HG + l6];
    float hcur = hidden[dir * HG + l6];

    const float4* gp = g_gi4 + (size_t)dir * LSEQ * HG + l6;

    float4 buf[8];
#pragma unroll
    for (int k = 0; k < 8; k++) buf[k] = __ldg(gp + k * HG);

    for (int t = 0; t < LSEQ; t += 8) {
#pragma unroll
        for (int k = 0; k < 8; k++) {
            float4 gi = buf[k];
            int tn = t + 8 + k;
            if (tn < LSEQ) buf[k] = __ldg(gp + (size_t)tn * HG);

            // precompute gate accumulator seeds off the critical path
            float ar0 = gi.x + br;     // r seed (bih_r + bhh_r folded)
            float az0 = gi.y + bz;     // z seed

            float h0 = __shfl_sync(FULL, hcur, 0);
            float h1 = __shfl_sync(FULL, hcur, 1);
            float h2 = __shfl_sync(FULL, hcur, 2);
            float h3 = __shfl_sync(FULL, hcur, 3);
            float h4 = __shfl_sync(FULL, hcur, 4);
            float h5 = __shfl_sync(FULL, hcur, 5);

            // r-gate dot (two parallel half-chains)
            float ra = fmaf(wr[0], h0, ar0); ra = fmaf(wr[1], h1, ra); ra = fmaf(wr[2], h2, ra);
            float rb = wr[3] * h3;           rb = fmaf(wr[4], h4, rb); rb = fmaf(wr[5], h5, rb);
            float xr = ra + rb;
            // z-gate dot
            float za = fmaf(wz[0], h0, az0); za = fmaf(wz[1], h1, za); za = fmaf(wz[2], h2, za);
            float zb = wz[3] * h3;           zb = fmaf(wz[4], h4, zb); zb = fmaf(wz[5], h5, zb);
            float xz = za + zb;
            // n-gate hidden dot (gh only; bhh_n included, bih_n NOT)
            float na = fmaf(wn[0], h0, bn);  na = fmaf(wn[1], h1, na); na = fmaf(wn[2], h2, na);
            float nb = wn[3] * h3;           nb = fmaf(wn[4], h4, nb); nb = fmaf(wn[5], h5, nb);
            float ghn = na + nb;

            // sigmoid(x) = 0.5*tanh(0.5x) + 0.5   (single MUFU each)
            float r = fmaf(0.5f, tanh_mufu(0.5f * xr), 0.5f);
            float z = fmaf(0.5f, tanh_mufu(0.5f * xz), 0.5f);

            float narg = fmaf(r, ghn, gi.z);
            float n = tanh_mufu(narg);
            hcur = fmaf(z, hcur - n, n);      // (1-z)*n + z*h

            if (dir == 1 && (t + k) == 0 && lane < HG) g_hb1[lane] = hcur;
        }
    }
    if (lane < HG) {
        if (dir == 0) g_hf[lane] = hcur;
        else          g_hb[lane] = hcur;
    }
}

// ------------------------- K5: combine chunks + epilogue --------------------
__global__ void k_final(const float* __restrict__ ipw, const float* __restrict__ c1w,
                        const float* __restrict__ c1b, const float* __restrict__ xpw,
                        const float* __restrict__ opw, const float* __restrict__ Dp,
                        const float* __restrict__ lw,  const float* __restrict__ lb,
                        float* __restrict__ out, int out_size)
{
    __shared__ float hs[NPAIR];
    __shared__ float us[DI], sres[DI], cs[DS], gs[DI], os[DM];
    int tid = threadIdx.x;

    if (tid < NPAIR) {
        float h = 0.0f;
#pragma unroll 4
        for (int ch = 0; ch < NCHUNK; ch++)
            h = fmaf(g_cA[ch * NPAIR + tid], h, g_cB[ch * NPAIR + tid]);
        hs[tid] = h;
    }
    __syncthreads();

    if (tid < DI) {
        int d = tid;
        float wr[DM];
#pragma unroll
        for (int w = 0; w < DM; w++) wr[w] = ipw[d * DM + w];
        float conv = 0.0f;
#pragma unroll
        for (int k = 0; k < 4; k++) {
            const float* srow = g_seq + (LSEQ - 4 + k) * DM;   // t = L-4+k
            float xm = 0.0f;
#pragma unroll
            for (int w = 0; w < DM; w++) xm = fmaf(srow[w], wr[w], xm);
            conv = fmaf(xm, c1w[d * 4 + k], conv);
        }
        float xc = conv + c1b[d];
        us[d] = xc * sigm(xc);

        float rr = 0.0f;
        const float* sl = g_seq + (LSEQ - 1) * DM;
#pragma unroll
        for (int w = 0; w < DM; w++) rr = fmaf(sl[w], ipw[(DI + d) * DM + w], rr);
        sres[d] = rr * sigm(rr);
    }
    __syncthreads();

    if (tid < DS) {                           // C at t=L-1
        float a = 0.0f;
#pragma unroll
        for (int d = 0; d < DI; d++) a = fmaf(us[d], xpw[(17 + tid) * DI + d], a);
        cs[tid] = a;
    }
    __syncthreads();

    if (tid < DI) {                           // y[L-1] and gate
        float y = 0.0f;
#pragma unroll
        for (int n = 0; n < DS; n++) y = fmaf(hs[tid * DS + n], cs[n], y);
        y = fmaf(us[tid], Dp[tid], y);
        gs[tid] = y * sres[tid];
    }
    __syncthreads();

    if (tid < DM) {                           // out1[L-1] + out2[L-1]
        float o = 0.0f;
#pragma unroll
        for (int d = 0; d < DI; d++) o = fmaf(gs[d], opw[tid * DI + d], o);
        o += (tid < 6) ? g_hf[tid] : g_hb1[tid - 6];
        os[tid] = o;
    }
    __syncthreads();

    if (tid == 0) {
        float p = lb[0];
#pragma unroll
        for (int w = 0; w < DM; w++) p = fmaf(os[w], lw[w], p);
        if (out_size > 0) out[0] = p;
    }
    if (tid < 6) {
        if (1 + tid < out_size) out[1 + tid] = g_hf[tid];
        if (7 + tid < out_size) out[7 + tid] = g_hb[tid];
    }
}

// ------------------------- launch -------------------------------------------
extern "C" void kernel_launch(void* const* d_in, const int* in_sizes, int n_in,
                              void* d_out, int out_size)
{
    const float* x    = (const float*)d_in[0];
    const float* hid  = (const float*)d_in[1];
    const float* c1w_ = (const float*)d_in[2];
    const float* c1b_ = (const float*)d_in[3];
    const float* bg1  = (const float*)d_in[4];
    const float* bb1  = (const float*)d_in[5];
    const float* bm1  = (const float*)d_in[6];
    const float* bv1  = (const float*)d_in[7];
    const float* c2w  = (const float*)d_in[8];
    const float* c2b  = (const float*)d_in[9];
    const float* bg2  = (const float*)d_in[10];
    const float* bb2  = (const float*)d_in[11];
    const float* bm2  = (const float*)d_in[12];
    const float* bv2  = (const float*)d_in[13];
    const float* ipw  = (const float*)d_in[14];
    const float* cd1w = (const float*)d_in[15];
    const float* cd1b = (const float*)d_in[16];
    const float* xpw  = (const float*)d_in[17];
    const float* dtw  = (const float*)d_in[18];
    const float* dtb  = (const float*)d_in[19];
    const float* Alog = (const float*)d_in[20];
    const float* Dp   = (const float*)d_in[21];
    const float* opw  = (const float*)d_in[22];
    const float* Wih  = (const float*)d_in[23];
    const float* Whh  = (const float*)d_in[24];
    const float* bih  = (const float*)d_in[25];
    const float* bhh  = (const float*)d_in[26];
    const float* lw   = (const float*)d_in[27];
    const float* lb   = (const float*)d_in[28];
    float* out = (float*)d_out;

    k_seq<<<(LSEQ * DM) / 256, 256>>>(x, c1w_, c1b_, bg1, bb1, bm1, bv1,
                                      c2w, c2b, bg2, bb2, bm2, bv2);
    k_gi<<<(2 * LSEQ) / 256, 256>>>(Wih, bih);
    k_chunk<<<NCHUNK, 384>>>(ipw, cd1w, cd1b, xpw, dtw, dtb, Alog);
    k_gru<<<2, 32>>>(Whh, bhh, hid);
    k_final<<<1, 384>>>(ipw, cd1w, cd1b, xpw, opw, Dp, lw, lb, out, out_size);
}